// round 4
// baseline (speedup 1.0000x reference)
#include <cuda_runtime.h>
#include <cuda_bf16.h>
#include <cstdint>

#define NTOK 8192
#define DIM  1024
#define NEXP 8
#define HID  4096
#define PADTOK (NTOK + 128)

// ===================== helpers =====================
__device__ __forceinline__ uint32_t smem_u32(const void* p) {
    uint32_t a;
    asm("{ .reg .u64 t; cvta.to.shared.u64 t, %1; cvt.u32.u64 %0, t; }" : "=r"(a) : "l"(p));
    return a;
}
__device__ __forceinline__ void cp16(uint32_t dst, const void* src) {
    asm volatile("cp.async.cg.shared.global [%0], [%1], 16;" :: "r"(dst), "l"(src) : "memory");
}
#define CP_COMMIT() asm volatile("cp.async.commit_group;" ::: "memory")
#define CP_WAIT2()  asm volatile("cp.async.wait_group 2;" ::: "memory")

__device__ __forceinline__ void ldsm4(uint32_t& r0, uint32_t& r1, uint32_t& r2, uint32_t& r3,
                                      uint32_t addr) {
    asm volatile("ldmatrix.sync.aligned.m8n8.x4.shared.b16 {%0,%1,%2,%3}, [%4];"
                 : "=r"(r0), "=r"(r1), "=r"(r2), "=r"(r3) : "r"(addr));
}
__device__ __forceinline__ void mma16816(float& c0, float& c1, float& c2, float& c3,
                                         uint32_t a0, uint32_t a1, uint32_t a2, uint32_t a3,
                                         uint32_t b0, uint32_t b1) {
    asm volatile(
        "mma.sync.aligned.m16n8k16.row.col.f32.bf16.bf16.f32 "
        "{%0,%1,%2,%3}, {%4,%5,%6,%7}, {%8,%9}, {%0,%1,%2,%3};"
        : "+f"(c0), "+f"(c1), "+f"(c2), "+f"(c3)
        : "r"(a0), "r"(a1), "r"(a2), "r"(a3), "r"(b0), "r"(b1));
}

__device__ __forceinline__ void split_bf16(float v, __nv_bfloat16& h, __nv_bfloat16& l) {
    h = __float2bfloat16_rn(v);
    l = __float2bfloat16_rn(v - __bfloat162float(h));
}

// ===================== device scratch =====================
__device__ int g_top1[NTOK];
__device__ int g_pos[NTOK];
__device__ int g_cnt[NEXP];
__device__ int g_off[NEXP];
__device__ int g_perm[NTOK];

__device__ __nv_bfloat16 g_xa_hi[(size_t)PADTOK * DIM];
__device__ __nv_bfloat16 g_xa_lo[(size_t)PADTOK * DIM];
__device__ __nv_bfloat16 g_h_hi[(size_t)PADTOK * HID];
__device__ __nv_bfloat16 g_h_lo[(size_t)PADTOK * HID];
__device__ __nv_bfloat16 g_w1_hi[(size_t)NEXP * HID * DIM];   // [e][n(HID)][k(DIM)]
__device__ __nv_bfloat16 g_w1_lo[(size_t)NEXP * HID * DIM];
__device__ __nv_bfloat16 g_w2_hi[(size_t)NEXP * DIM * HID];   // [e][n(DIM)][k(HID)]
__device__ __nv_bfloat16 g_w2_lo[(size_t)NEXP * DIM * HID];

// ===================== gating =====================
__global__ void zero_counts_kernel() {
    if (threadIdx.x < NEXP) g_cnt[threadIdx.x] = 0;
}

__global__ void gate_kernel(const float* __restrict__ x,
                            const float* __restrict__ gw,
                            const float* __restrict__ gb) {
    int warp = blockIdx.x * (blockDim.x / 32) + (threadIdx.x >> 5);
    int lane = threadIdx.x & 31;
    if (warp >= NTOK) return;
    const float* xr = x + (size_t)warp * DIM;
    float acc[NEXP];
#pragma unroll
    for (int e = 0; e < NEXP; e++) acc[e] = 0.f;
    for (int d = lane; d < DIM; d += 32) {
        float xv = xr[d];
        const float4* g4 = reinterpret_cast<const float4*>(gw + (size_t)d * NEXP);
        float4 g0 = g4[0], g1 = g4[1];
        acc[0] += xv * g0.x; acc[1] += xv * g0.y; acc[2] += xv * g0.z; acc[3] += xv * g0.w;
        acc[4] += xv * g1.x; acc[5] += xv * g1.y; acc[6] += xv * g1.z; acc[7] += xv * g1.w;
    }
#pragma unroll
    for (int e = 0; e < NEXP; e++) {
#pragma unroll
        for (int o = 16; o > 0; o >>= 1) acc[e] += __shfl_xor_sync(0xffffffffu, acc[e], o);
    }
    if (lane == 0) {
        int best = 0; float bv = acc[0] + gb[0];
#pragma unroll
        for (int e = 1; e < NEXP; e++) {
            float v = acc[e] + gb[e];
            if (v > bv) { bv = v; best = e; }
        }
        g_top1[warp] = best;
        g_pos[warp]  = atomicAdd(&g_cnt[best], 1);
    }
}

__global__ void scan_offsets_kernel() {
    int off = 0;
    for (int e = 0; e < NEXP; e++) { g_off[e] = off; off += g_cnt[e]; }
}

__global__ void scatter_kernel() {
    int n = blockIdx.x * blockDim.x + threadIdx.x;
    if (n >= NTOK) return;
    g_perm[g_off[g_top1[n]] + g_pos[n]] = n;
}

// ===================== conversions =====================
__global__ void conv_x_kernel(const float* __restrict__ x) {
    int s = blockIdx.x;
    int tok = g_perm[s];
    int t = threadIdx.x;
    float4 v = reinterpret_cast<const float4*>(x + (size_t)tok * DIM)[t];
    __nv_bfloat16 h0, l0, h1, l1, h2, l2, h3, l3;
    split_bf16(v.x, h0, l0); split_bf16(v.y, h1, l1);
    split_bf16(v.z, h2, l2); split_bf16(v.w, h3, l3);
    size_t o = (size_t)s * DIM + t * 4;
    reinterpret_cast<__nv_bfloat162*>(g_xa_hi + o)[0] = __nv_bfloat162(h0, h1);
    reinterpret_cast<__nv_bfloat162*>(g_xa_hi + o)[1] = __nv_bfloat162(h2, h3);
    reinterpret_cast<__nv_bfloat162*>(g_xa_lo + o)[0] = __nv_bfloat162(l0, l1);
    reinterpret_cast<__nv_bfloat162*>(g_xa_lo + o)[1] = __nv_bfloat162(l2, l3);
}

// weights [e][R][C] fp32 -> transposed [e][C][R] bf16 hi/lo (K-major for MMA)
template<int R, int C, bool W1>
__global__ void conv_w_kernel(const float* __restrict__ in) {
    __shared__ float tile[32][33];
    int e = blockIdx.z;
    int r0 = blockIdx.y * 32, c0 = blockIdx.x * 32;
    const float* src = in + ((size_t)e * R + r0) * C + c0;
#pragma unroll
    for (int j = threadIdx.y; j < 32; j += 8)
        tile[j][threadIdx.x] = src[(size_t)j * C + threadIdx.x];
    __syncthreads();
    __nv_bfloat16* oh = (W1 ? g_w1_hi : g_w2_hi) + ((size_t)e * C + c0) * R + r0;
    __nv_bfloat16* ol = (W1 ? g_w1_lo : g_w2_lo) + ((size_t)e * C + c0) * R + r0;
#pragma unroll
    for (int j = threadIdx.y; j < 32; j += 8) {
        float v = tile[threadIdx.x][j];
        __nv_bfloat16 h, l;
        split_bf16(v, h, l);
        oh[(size_t)j * R + threadIdx.x] = h;
        ol[(size_t)j * R + threadIdx.x] = l;
    }
}

// ===================== mma.sync GEMM =====================
// CTA tile 128(M) x 128(N); 8 warps (2M x 4N), warp tile 64x32.
// K chunk = 64 bf16 (128B rows). 3-stage cp.async pipeline (192KB smem).
// 3-pass hi/lo: C += Ahi*Bhi + Alo*Bhi + Ahi*Blo (fp32 accum).
#define AHI 0
#define ALO 16384
#define BHI 32768
#define BLO 49152
#define STAGE 65536
#define NSTAGE 3

template<bool FIRST>
__global__ __launch_bounds__(256, 1)
void moe_gemm(const float* __restrict__ bias,
              const float* __restrict__ x,
              float* __restrict__ out) {
    constexpr int KDIM = FIRST ? DIM : HID;
    constexpr int NDIM = FIRST ? HID : DIM;
    constexpr int NKC  = KDIM / 64;

    const int e  = blockIdx.z;
    const int Me = g_cnt[e];
    const int m0 = blockIdx.y * 128;
    if (m0 >= Me) return;
    const int off = g_off[e];
    const int n0  = blockIdx.x * 128;

    const __nv_bfloat16* Ahi = FIRST ? g_xa_hi : g_h_hi;
    const __nv_bfloat16* Alo = FIRST ? g_xa_lo : g_h_lo;
    const __nv_bfloat16* Whi = (FIRST ? g_w1_hi : g_w2_hi) + (size_t)e * NDIM * KDIM;
    const __nv_bfloat16* Wlo = (FIRST ? g_w1_lo : g_w2_lo) + (size_t)e * NDIM * KDIM;

    extern __shared__ char smem[];
    const uint32_t sb = smem_u32(smem);

    const int tid  = threadIdx.x;
    const int lane = tid & 31;
    const int wid  = tid >> 5;
    const int wrow = wid & 1;           // M offset 0/64
    const int wcol = wid >> 1;          // N offset 0/32/64/96

    // ---- async load of one K-chunk into a stage ----
    auto issue_loads = [&](int chunk) {
        const uint32_t base = sb + (chunk % NSTAGE) * STAGE;
        const int k0 = chunk * 64;
#pragma unroll
        for (int w = 0; w < 4; w++) {
            int idx = w * 256 + tid;           // 0..1023
            int row = idx >> 3;                // 0..127
            int c8  = idx & 7;                 // 16B chunk in row
            uint32_t sw = (uint32_t)(row * 128 + ((c8 * 16) ^ ((row & 7) << 4)));
            const __nv_bfloat16* a_h = Ahi + (size_t)(off + m0 + row) * KDIM + k0 + c8 * 8;
            const __nv_bfloat16* a_l = Alo + (size_t)(off + m0 + row) * KDIM + k0 + c8 * 8;
            const __nv_bfloat16* b_h = Whi + (size_t)(n0 + row) * KDIM + k0 + c8 * 8;
            const __nv_bfloat16* b_l = Wlo + (size_t)(n0 + row) * KDIM + k0 + c8 * 8;
            cp16(base + AHI + sw, a_h);
            cp16(base + ALO + sw, a_l);
            cp16(base + BHI + sw, b_h);
            cp16(base + BLO + sw, b_l);
        }
    };

    // ---- per-lane ldmatrix geometry ----
    const int sel = lane >> 3;          // which 8x8 matrix this lane addresses
    const int l7  = lane & 7;
    const uint32_t lxor = (uint32_t)(l7 << 4);   // swizzle xor
    uint32_t arow[4], brow[2];
#pragma unroll
    for (int mf = 0; mf < 4; mf++)
        arow[mf] = (uint32_t)((wrow * 64 + mf * 16 + (sel & 1) * 8 + l7) * 128);
#pragma unroll
    for (int nb = 0; nb < 2; nb++)
        brow[nb] = (uint32_t)((wcol * 32 + nb * 16 + (sel >> 1) * 8 + l7) * 128);
    const uint32_t acb = (uint32_t)((sel >> 1) * 16);   // A: k+8 select
    const uint32_t bcb = (uint32_t)((sel & 1) * 16);    // B: k+8 select

    float c[4][4][4];
#pragma unroll
    for (int i = 0; i < 4; i++)
#pragma unroll
        for (int j = 0; j < 4; j++)
#pragma unroll
            for (int r = 0; r < 4; r++) c[i][j][r] = 0.f;

    issue_loads(0); CP_COMMIT();
    issue_loads(1); CP_COMMIT();

    for (int i = 0; i < NKC; i++) {
        if (i + 2 < NKC) issue_loads(i + 2);
        CP_COMMIT();
        CP_WAIT2();                      // <=2 pending -> chunk i resident
        __syncthreads();

        const uint32_t base = sb + (i % NSTAGE) * STAGE;
#pragma unroll
        for (int kk = 0; kk < 4; kk++) {
            const uint32_t colA = (acb + kk * 32) ^ lxor;
            const uint32_t colB = (bcb + kk * 32) ^ lxor;

            uint32_t Ah[4][4], Al[4][4], Bh[2][4], Bl[2][4];
#pragma unroll
            for (int mf = 0; mf < 4; mf++)
                ldsm4(Ah[mf][0], Ah[mf][1], Ah[mf][2], Ah[mf][3], base + AHI + arow[mf] + colA);
#pragma unroll
            for (int nb = 0; nb < 2; nb++)
                ldsm4(Bh[nb][0], Bh[nb][1], Bh[nb][2], Bh[nb][3], base + BHI + brow[nb] + colB);
            // pass 1: Ahi * Bhi
#pragma unroll
            for (int mf = 0; mf < 4; mf++)
#pragma unroll
                for (int nb = 0; nb < 2; nb++)
#pragma unroll
                    for (int h = 0; h < 2; h++)
                        mma16816(c[mf][nb*2+h][0], c[mf][nb*2+h][1], c[mf][nb*2+h][2], c[mf][nb*2+h][3],
                                 Ah[mf][0], Ah[mf][1], Ah[mf][2], Ah[mf][3],
                                 Bh[nb][2*h], Bh[nb][2*h+1]);
            // pass 2: Alo * Bhi
#pragma unroll
            for (int mf = 0; mf < 4; mf++)
                ldsm4(Al[mf][0], Al[mf][1], Al[mf][2], Al[mf][3], base + ALO + arow[mf] + colA);
#pragma unroll
            for (int mf = 0; mf < 4; mf++)
#pragma unroll
                for (int nb = 0; nb < 2; nb++)
#pragma unroll
                    for (int h = 0; h < 2; h++)
                        mma16816(c[mf][nb*2+h][0], c[mf][nb*2+h][1], c[mf][nb*2+h][2], c[mf][nb*2+h][3],
                                 Al[mf][0], Al[mf][1], Al[mf][2], Al[mf][3],
                                 Bh[nb][2*h], Bh[nb][2*h+1]);
            // pass 3: Ahi * Blo
#pragma unroll
            for (int nb = 0; nb < 2; nb++)
                ldsm4(Bl[nb][0], Bl[nb][1], Bl[nb][2], Bl[nb][3], base + BLO + brow[nb] + colB);
#pragma unroll
            for (int mf = 0; mf < 4; mf++)
#pragma unroll
                for (int nb = 0; nb < 2; nb++)
#pragma unroll
                    for (int h = 0; h < 2; h++)
                        mma16816(c[mf][nb*2+h][0], c[mf][nb*2+h][1], c[mf][nb*2+h][2], c[mf][nb*2+h][3],
                                 Ah[mf][0], Ah[mf][1], Ah[mf][2], Ah[mf][3],
                                 Bl[nb][2*h], Bl[nb][2*h+1]);
        }
        __syncthreads();
    }

    // ---- epilogue from registers ----
    const int gr = lane >> 2;           // 0..7 row within 8
    const int gc = (lane & 3) * 2;      // even col within 8
    const float* B = bias + (size_t)e * NDIM;

#pragma unroll
    for (int mf = 0; mf < 4; mf++) {
#pragma unroll
        for (int half = 0; half < 2; half++) {
            const int ml = wrow * 64 + mf * 16 + half * 8 + gr;
            if (m0 + ml >= Me) continue;
            const int slot = off + m0 + ml;
#pragma unroll
            for (int nf = 0; nf < 4; nf++) {
                const int n = n0 + wcol * 32 + nf * 8 + gc;
                const float2 bv = *reinterpret_cast<const float2*>(B + n);
                float v0 = c[mf][nf][half * 2 + 0] + bv.x;
                float v1 = c[mf][nf][half * 2 + 1] + bv.y;
                if (FIRST) {
                    v0 = fmaxf(v0, 0.f);
                    v1 = fmaxf(v1, 0.f);
                    __nv_bfloat16 h0, l0, h1, l1;
                    split_bf16(v0, h0, l0); split_bf16(v1, h1, l1);
                    size_t o = (size_t)slot * HID + n;
                    *reinterpret_cast<__nv_bfloat162*>(g_h_hi + o) = __nv_bfloat162(h0, h1);
                    *reinterpret_cast<__nv_bfloat162*>(g_h_lo + o) = __nv_bfloat162(l0, l1);
                } else {
                    const int tok = g_perm[slot];
                    const float2 xv = *reinterpret_cast<const float2*>(x + (size_t)tok * DIM + n);
                    float2 ov = make_float2(v0 + xv.x, v1 + xv.y);
                    *reinterpret_cast<float2*>(out + (size_t)tok * DIM + n) = ov;
                }
            }
        }
    }
}

// ===================== launch =====================
extern "C" void kernel_launch(void* const* d_in, const int* in_sizes, int n_in,
                              void* d_out, int out_size) {
    const float* x  = (const float*)d_in[0];
    const float* gw = (const float*)d_in[1];
    const float* gb = (const float*)d_in[2];
    const float* w1 = (const float*)d_in[3];
    const float* b1 = (const float*)d_in[4];
    const float* w2 = (const float*)d_in[5];
    const float* b2 = (const float*)d_in[6];
    float* out = (float*)d_out;

    const int SMEM_BYTES = NSTAGE * STAGE;   // 192KB
    cudaFuncSetAttribute(moe_gemm<true>,  cudaFuncAttributeMaxDynamicSharedMemorySize, SMEM_BYTES);
    cudaFuncSetAttribute(moe_gemm<false>, cudaFuncAttributeMaxDynamicSharedMemorySize, SMEM_BYTES);

    zero_counts_kernel<<<1, 32>>>();
    gate_kernel<<<NTOK / 8, 256>>>(x, gw, gb);
    scan_offsets_kernel<<<1, 1>>>();
    scatter_kernel<<<NTOK / 256, 256>>>();

    conv_x_kernel<<<NTOK, 256>>>(x);
    conv_w_kernel<DIM, HID, true ><<<dim3(HID / 32, DIM / 32, NEXP), dim3(32, 8)>>>(w1);
    conv_w_kernel<HID, DIM, false><<<dim3(DIM / 32, HID / 32, NEXP), dim3(32, 8)>>>(w2);

    // GEMM1: [slots x HID], K=DIM
    moe_gemm<true ><<<dim3(HID / 128, NTOK / 128, NEXP), 256, SMEM_BYTES>>>(b1, x, nullptr);
    // GEMM2: [slots x DIM], K=HID
    moe_gemm<false><<<dim3(DIM / 128, NTOK / 128, NEXP), 256, SMEM_BYTES>>>(b2, x, out);
}

// round 5
// speedup vs baseline: 1.4699x; 1.4699x over previous
#include <cuda_runtime.h>
#include <cuda_fp16.h>
#include <cstdint>

#define NTOK 8192
#define DIM  1024
#define NEXP 8
#define HID  4096
#define PADTOK (NTOK + 128)

// ===================== helpers =====================
__device__ __forceinline__ uint32_t smem_u32(const void* p) {
    uint32_t a;
    asm("{ .reg .u64 t; cvta.to.shared.u64 t, %1; cvt.u32.u64 %0, t; }" : "=r"(a) : "l"(p));
    return a;
}
__device__ __forceinline__ void cp16(uint32_t dst, const void* src) {
    asm volatile("cp.async.cg.shared.global [%0], [%1], 16;" :: "r"(dst), "l"(src) : "memory");
}
#define CP_COMMIT() asm volatile("cp.async.commit_group;" ::: "memory")
#define CP_WAIT2()  asm volatile("cp.async.wait_group 2;" ::: "memory")

__device__ __forceinline__ void ldsm4(uint32_t& r0, uint32_t& r1, uint32_t& r2, uint32_t& r3,
                                      uint32_t addr) {
    asm volatile("ldmatrix.sync.aligned.m8n8.x4.shared.b16 {%0,%1,%2,%3}, [%4];"
                 : "=r"(r0), "=r"(r1), "=r"(r2), "=r"(r3) : "r"(addr));
}
__device__ __forceinline__ void mma16816(float& c0, float& c1, float& c2, float& c3,
                                         uint32_t a0, uint32_t a1, uint32_t a2, uint32_t a3,
                                         uint32_t b0, uint32_t b1) {
    asm volatile(
        "mma.sync.aligned.m16n8k16.row.col.f32.f16.f16.f32 "
        "{%0,%1,%2,%3}, {%4,%5,%6,%7}, {%8,%9}, {%0,%1,%2,%3};"
        : "+f"(c0), "+f"(c1), "+f"(c2), "+f"(c3)
        : "r"(a0), "r"(a1), "r"(a2), "r"(a3), "r"(b0), "r"(b1));
}

__device__ __forceinline__ void split_f16(float v, __half& h, __half& l) {
    h = __float2half_rn(v);
    l = __float2half_rn(v - __half2float(h));
}

// ===================== device scratch =====================
__device__ int g_top1[NTOK];
__device__ int g_pos[NTOK];
__device__ int g_cnt[NEXP];
__device__ int g_off[NEXP];
__device__ int g_perm[NTOK];

__device__ __half g_xa_hi[(size_t)PADTOK * DIM];
__device__ __half g_xa_lo[(size_t)PADTOK * DIM];
__device__ __half g_h_hi[(size_t)PADTOK * HID];
__device__ __half g_h_lo[(size_t)PADTOK * HID];
__device__ __half g_w1[(size_t)NEXP * HID * DIM];   // [e][n(HID)][k(DIM)]  fp16
__device__ __half g_w2[(size_t)NEXP * DIM * HID];   // [e][n(DIM)][k(HID)]  fp16

// ===================== gating =====================
__global__ void zero_counts_kernel() {
    if (threadIdx.x < NEXP) g_cnt[threadIdx.x] = 0;
}

__global__ void gate_kernel(const float* __restrict__ x,
                            const float* __restrict__ gw,
                            const float* __restrict__ gb) {
    int warp = blockIdx.x * (blockDim.x / 32) + (threadIdx.x >> 5);
    int lane = threadIdx.x & 31;
    if (warp >= NTOK) return;
    const float* xr = x + (size_t)warp * DIM;
    float acc[NEXP];
#pragma unroll
    for (int e = 0; e < NEXP; e++) acc[e] = 0.f;
    for (int d = lane; d < DIM; d += 32) {
        float xv = xr[d];
        const float4* g4 = reinterpret_cast<const float4*>(gw + (size_t)d * NEXP);
        float4 g0 = g4[0], g1 = g4[1];
        acc[0] += xv * g0.x; acc[1] += xv * g0.y; acc[2] += xv * g0.z; acc[3] += xv * g0.w;
        acc[4] += xv * g1.x; acc[5] += xv * g1.y; acc[6] += xv * g1.z; acc[7] += xv * g1.w;
    }
#pragma unroll
    for (int e = 0; e < NEXP; e++) {
#pragma unroll
        for (int o = 16; o > 0; o >>= 1) acc[e] += __shfl_xor_sync(0xffffffffu, acc[e], o);
    }
    if (lane == 0) {
        int best = 0; float bv = acc[0] + gb[0];
#pragma unroll
        for (int e = 1; e < NEXP; e++) {
            float v = acc[e] + gb[e];
            if (v > bv) { bv = v; best = e; }
        }
        g_top1[warp] = best;
        g_pos[warp]  = atomicAdd(&g_cnt[best], 1);
    }
}

__global__ void scan_offsets_kernel() {
    int off = 0;
    for (int e = 0; e < NEXP; e++) { g_off[e] = off; off += g_cnt[e]; }
}

__global__ void scatter_kernel() {
    int n = blockIdx.x * blockDim.x + threadIdx.x;
    if (n >= NTOK) return;
    g_perm[g_off[g_top1[n]] + g_pos[n]] = n;
}

// ===================== conversions =====================
__global__ void conv_x_kernel(const float* __restrict__ x) {
    int s = blockIdx.x;
    int tok = g_perm[s];
    int t = threadIdx.x;
    float4 v = reinterpret_cast<const float4*>(x + (size_t)tok * DIM)[t];
    __half h0, l0, h1, l1, h2, l2, h3, l3;
    split_f16(v.x, h0, l0); split_f16(v.y, h1, l1);
    split_f16(v.z, h2, l2); split_f16(v.w, h3, l3);
    size_t o = (size_t)s * DIM + t * 4;
    reinterpret_cast<__half2*>(g_xa_hi + o)[0] = __half2(h0, h1);
    reinterpret_cast<__half2*>(g_xa_hi + o)[1] = __half2(h2, h3);
    reinterpret_cast<__half2*>(g_xa_lo + o)[0] = __half2(l0, l1);
    reinterpret_cast<__half2*>(g_xa_lo + o)[1] = __half2(l2, l3);
}

// weights [e][R][C] fp32 -> transposed [e][C][R] fp16 (K-major for MMA)
template<int R, int C, bool W1>
__global__ void conv_w_kernel(const float* __restrict__ in) {
    __shared__ float tile[32][33];
    int e = blockIdx.z;
    int r0 = blockIdx.y * 32, c0 = blockIdx.x * 32;
    const float* src = in + ((size_t)e * R + r0) * C + c0;
#pragma unroll
    for (int j = threadIdx.y; j < 32; j += 8)
        tile[j][threadIdx.x] = src[(size_t)j * C + threadIdx.x];
    __syncthreads();
    __half* o = (W1 ? g_w1 : g_w2) + ((size_t)e * C + c0) * R + r0;
#pragma unroll
    for (int j = threadIdx.y; j < 32; j += 8)
        o[(size_t)j * R + threadIdx.x] = __float2half_rn(tile[threadIdx.x][j]);
}

// ===================== mma.sync GEMM =====================
// CTA tile 128(M) x 256(N); 8 warps (2M x 4N), warp tile 64x64.
// K chunk = 64 fp16 (128B rows). 3-stage cp.async pipeline (192KB smem).
// 2-pass split-A fp16: C += Ahi*B + Alo*B (fp32 accum).
#define AHI 0
#define ALO 16384
#define BOFF 32768
#define STAGE 65536
#define NSTAGE 3

template<bool FIRST>
__global__ __launch_bounds__(256, 1)
void moe_gemm(const float* __restrict__ bias,
              const float* __restrict__ x,
              float* __restrict__ out) {
    constexpr int KDIM = FIRST ? DIM : HID;
    constexpr int NDIM = FIRST ? HID : DIM;
    constexpr int NKC  = KDIM / 64;

    const int e  = blockIdx.z;
    const int Me = g_cnt[e];
    const int m0 = blockIdx.y * 128;
    if (m0 >= Me) return;
    const int off = g_off[e];
    const int n0  = blockIdx.x * 256;

    const __half* Ahi = FIRST ? g_xa_hi : g_h_hi;
    const __half* Alo = FIRST ? g_xa_lo : g_h_lo;
    const __half* W   = (FIRST ? g_w1 : g_w2) + (size_t)e * NDIM * KDIM;

    extern __shared__ char smem[];
    const uint32_t sb = smem_u32(smem);

    const int tid  = threadIdx.x;
    const int lane = tid & 31;
    const int wid  = tid >> 5;
    const int wrow = wid & 1;           // M offset 0/64
    const int wcol = wid >> 1;          // N offset 0/64/128/192

    // ---- async load of one K-chunk into a stage ----
    auto issue_loads = [&](int chunk) {
        const uint32_t base = sb + (chunk % NSTAGE) * STAGE;
        const int k0 = chunk * 64;
        // A hi+lo: 128 rows x 8 x 16B each
#pragma unroll
        for (int w = 0; w < 4; w++) {
            int idx = w * 256 + tid;           // 0..1023
            int row = idx >> 3;                // 0..127
            int c8  = idx & 7;
            uint32_t sw = (uint32_t)(row * 128 + ((c8 * 16) ^ ((row & 7) << 4)));
            const __half* a_h = Ahi + (size_t)(off + m0 + row) * KDIM + k0 + c8 * 8;
            const __half* a_l = Alo + (size_t)(off + m0 + row) * KDIM + k0 + c8 * 8;
            cp16(base + AHI + sw, a_h);
            cp16(base + ALO + sw, a_l);
        }
        // B: 256 rows x 8 x 16B
#pragma unroll
        for (int w = 0; w < 8; w++) {
            int idx = w * 256 + tid;           // 0..2047
            int row = idx >> 3;                // 0..255
            int c8  = idx & 7;
            uint32_t sw = (uint32_t)(row * 128 + ((c8 * 16) ^ ((row & 7) << 4)));
            cp16(base + BOFF + sw, W + (size_t)(n0 + row) * KDIM + k0 + c8 * 8);
        }
    };

    // ---- per-lane ldmatrix geometry ----
    const int sel = lane >> 3;
    const int l7  = lane & 7;
    const uint32_t lxor = (uint32_t)(l7 << 4);
    uint32_t arow[4], brow[4];
#pragma unroll
    for (int mf = 0; mf < 4; mf++)
        arow[mf] = (uint32_t)((wrow * 64 + mf * 16 + (sel & 1) * 8 + l7) * 128);
#pragma unroll
    for (int nb = 0; nb < 4; nb++)
        brow[nb] = (uint32_t)((wcol * 64 + nb * 16 + (sel >> 1) * 8 + l7) * 128);
    const uint32_t acb = (uint32_t)((sel >> 1) * 16);
    const uint32_t bcb = (uint32_t)((sel & 1) * 16);

    float c[4][8][4];
#pragma unroll
    for (int i = 0; i < 4; i++)
#pragma unroll
        for (int j = 0; j < 8; j++)
#pragma unroll
            for (int r = 0; r < 4; r++) c[i][j][r] = 0.f;

    issue_loads(0); CP_COMMIT();
    issue_loads(1); CP_COMMIT();

    for (int i = 0; i < NKC; i++) {
        if (i + 2 < NKC) issue_loads(i + 2);
        CP_COMMIT();
        CP_WAIT2();
        __syncthreads();

        const uint32_t base = sb + (i % NSTAGE) * STAGE;
#pragma unroll
        for (int kk = 0; kk < 4; kk++) {
            const uint32_t colA = (acb + kk * 32) ^ lxor;
            const uint32_t colB = (bcb + kk * 32) ^ lxor;

            uint32_t Ah[4][4], Al[4][4], Bf[4][4];
#pragma unroll
            for (int mf = 0; mf < 4; mf++)
                ldsm4(Ah[mf][0], Ah[mf][1], Ah[mf][2], Ah[mf][3], base + AHI + arow[mf] + colA);
#pragma unroll
            for (int nb = 0; nb < 4; nb++)
                ldsm4(Bf[nb][0], Bf[nb][1], Bf[nb][2], Bf[nb][3], base + BOFF + brow[nb] + colB);
            // pass 1: Ahi * B
#pragma unroll
            for (int mf = 0; mf < 4; mf++)
#pragma unroll
                for (int nb = 0; nb < 4; nb++)
#pragma unroll
                    for (int h = 0; h < 2; h++)
                        mma16816(c[mf][nb*2+h][0], c[mf][nb*2+h][1], c[mf][nb*2+h][2], c[mf][nb*2+h][3],
                                 Ah[mf][0], Ah[mf][1], Ah[mf][2], Ah[mf][3],
                                 Bf[nb][2*h], Bf[nb][2*h+1]);
            // pass 2: Alo * B
#pragma unroll
            for (int mf = 0; mf < 4; mf++)
                ldsm4(Al[mf][0], Al[mf][1], Al[mf][2], Al[mf][3], base + ALO + arow[mf] + colA);
#pragma unroll
            for (int mf = 0; mf < 4; mf++)
#pragma unroll
                for (int nb = 0; nb < 4; nb++)
#pragma unroll
                    for (int h = 0; h < 2; h++)
                        mma16816(c[mf][nb*2+h][0], c[mf][nb*2+h][1], c[mf][nb*2+h][2], c[mf][nb*2+h][3],
                                 Al[mf][0], Al[mf][1], Al[mf][2], Al[mf][3],
                                 Bf[nb][2*h], Bf[nb][2*h+1]);
        }
        __syncthreads();
    }

    // ---- epilogue from registers ----
    const int gr = lane >> 2;
    const int gc = (lane & 3) * 2;
    const float* bs = bias + (size_t)e * NDIM;

#pragma unroll
    for (int mf = 0; mf < 4; mf++) {
#pragma unroll
        for (int half = 0; half < 2; half++) {
            const int ml = wrow * 64 + mf * 16 + half * 8 + gr;
            if (m0 + ml >= Me) continue;
            const int slot = off + m0 + ml;
#pragma unroll
            for (int nf = 0; nf < 8; nf++) {
                const int n = n0 + wcol * 64 + nf * 8 + gc;
                const float2 bv = *reinterpret_cast<const float2*>(bs + n);
                float v0 = c[mf][nf][half * 2 + 0] + bv.x;
                float v1 = c[mf][nf][half * 2 + 1] + bv.y;
                if (FIRST) {
                    v0 = fmaxf(v0, 0.f);
                    v1 = fmaxf(v1, 0.f);
                    __half h0, l0, h1, l1;
                    split_f16(v0, h0, l0); split_f16(v1, h1, l1);
                    size_t o = (size_t)slot * HID + n;
                    *reinterpret_cast<__half2*>(g_h_hi + o) = __half2(h0, h1);
                    *reinterpret_cast<__half2*>(g_h_lo + o) = __half2(l0, l1);
                } else {
                    const int tok = g_perm[slot];
                    const float2 xv = *reinterpret_cast<const float2*>(x + (size_t)tok * DIM + n);
                    float2 ov = make_float2(v0 + xv.x, v1 + xv.y);
                    *reinterpret_cast<float2*>(out + (size_t)tok * DIM + n) = ov;
                }
            }
        }
    }
}

// ===================== launch =====================
extern "C" void kernel_launch(void* const* d_in, const int* in_sizes, int n_in,
                              void* d_out, int out_size) {
    const float* x  = (const float*)d_in[0];
    const float* gw = (const float*)d_in[1];
    const float* gb = (const float*)d_in[2];
    const float* w1 = (const float*)d_in[3];
    const float* b1 = (const float*)d_in[4];
    const float* w2 = (const float*)d_in[5];
    const float* b2 = (const float*)d_in[6];
    float* out = (float*)d_out;

    const int SMEM_BYTES = NSTAGE * STAGE;   // 192KB
    cudaFuncSetAttribute(moe_gemm<true>,  cudaFuncAttributeMaxDynamicSharedMemorySize, SMEM_BYTES);
    cudaFuncSetAttribute(moe_gemm<false>, cudaFuncAttributeMaxDynamicSharedMemorySize, SMEM_BYTES);

    zero_counts_kernel<<<1, 32>>>();
    gate_kernel<<<NTOK / 8, 256>>>(x, gw, gb);
    scan_offsets_kernel<<<1, 1>>>();
    scatter_kernel<<<NTOK / 256, 256>>>();

    conv_x_kernel<<<NTOK, 256>>>(x);
    conv_w_kernel<DIM, HID, true ><<<dim3(HID / 32, DIM / 32, NEXP), dim3(32, 8)>>>(w1);
    conv_w_kernel<HID, DIM, false><<<dim3(DIM / 32, HID / 32, NEXP), dim3(32, 8)>>>(w2);

    // GEMM1: [slots x HID], K=DIM
    moe_gemm<true ><<<dim3(HID / 256, NTOK / 128, NEXP), 256, SMEM_BYTES>>>(b1, x, nullptr);
    // GEMM2: [slots x DIM], K=HID
    moe_gemm<false><<<dim3(DIM / 256, NTOK / 128, NEXP), 256, SMEM_BYTES>>>(b2, x, out);
}

// round 6
// speedup vs baseline: 2.1979x; 1.4953x over previous
#include <cuda_runtime.h>
#include <cuda_fp16.h>
#include <cstdint>

#define NTOK 8192
#define DIM  1024
#define NEXP 8
#define HID  4096
#define PADTOK (NTOK + 128)

// ===================== helpers =====================
__device__ __forceinline__ uint32_t smem_u32(const void* p) {
    uint32_t a;
    asm("{ .reg .u64 t; cvta.to.shared.u64 t, %1; cvt.u32.u64 %0, t; }" : "=r"(a) : "l"(p));
    return a;
}
__device__ __forceinline__ void cp16(uint32_t dst, const void* src) {
    asm volatile("cp.async.cg.shared.global [%0], [%1], 16;" :: "r"(dst), "l"(src) : "memory");
}
#define CP_COMMIT() asm volatile("cp.async.commit_group;" ::: "memory")
#define CP_WAIT3()  asm volatile("cp.async.wait_group 3;" ::: "memory")

__device__ __forceinline__ void ldsm4(uint32_t& r0, uint32_t& r1, uint32_t& r2, uint32_t& r3,
                                      uint32_t addr) {
    asm volatile("ldmatrix.sync.aligned.m8n8.x4.shared.b16 {%0,%1,%2,%3}, [%4];"
                 : "=r"(r0), "=r"(r1), "=r"(r2), "=r"(r3) : "r"(addr));
}
__device__ __forceinline__ void mma16816(float& c0, float& c1, float& c2, float& c3,
                                         uint32_t a0, uint32_t a1, uint32_t a2, uint32_t a3,
                                         uint32_t b0, uint32_t b1) {
    asm volatile(
        "mma.sync.aligned.m16n8k16.row.col.f32.f16.f16.f32 "
        "{%0,%1,%2,%3}, {%4,%5,%6,%7}, {%8,%9}, {%0,%1,%2,%3};"
        : "+f"(c0), "+f"(c1), "+f"(c2), "+f"(c3)
        : "r"(a0), "r"(a1), "r"(a2), "r"(a3), "r"(b0), "r"(b1));
}

// ===================== device scratch =====================
__device__ int g_top1[NTOK];
__device__ int g_pos[NTOK];
__device__ int g_cnt[NEXP];
__device__ int g_off[NEXP];
__device__ int g_perm[NTOK];

__device__ __half g_xa[(size_t)PADTOK * DIM];       // permuted x, fp16
__device__ __half g_h[(size_t)PADTOK * HID];        // hidden, fp16
__device__ __half g_w1[(size_t)NEXP * HID * DIM];   // [e][n(HID)][k(DIM)]
__device__ __half g_w2[(size_t)NEXP * DIM * HID];   // [e][n(DIM)][k(HID)]

// ===================== gating =====================
__global__ void zero_counts_kernel() {
    if (threadIdx.x < NEXP) g_cnt[threadIdx.x] = 0;
}

__global__ void gate_kernel(const float* __restrict__ x,
                            const float* __restrict__ gw,
                            const float* __restrict__ gb) {
    int warp = blockIdx.x * (blockDim.x / 32) + (threadIdx.x >> 5);
    int lane = threadIdx.x & 31;
    if (warp >= NTOK) return;
    const float* xr = x + (size_t)warp * DIM;
    float acc[NEXP];
#pragma unroll
    for (int e = 0; e < NEXP; e++) acc[e] = 0.f;
    for (int d = lane; d < DIM; d += 32) {
        float xv = xr[d];
        const float4* g4 = reinterpret_cast<const float4*>(gw + (size_t)d * NEXP);
        float4 g0 = g4[0], g1 = g4[1];
        acc[0] += xv * g0.x; acc[1] += xv * g0.y; acc[2] += xv * g0.z; acc[3] += xv * g0.w;
        acc[4] += xv * g1.x; acc[5] += xv * g1.y; acc[6] += xv * g1.z; acc[7] += xv * g1.w;
    }
#pragma unroll
    for (int e = 0; e < NEXP; e++) {
#pragma unroll
        for (int o = 16; o > 0; o >>= 1) acc[e] += __shfl_xor_sync(0xffffffffu, acc[e], o);
    }
    if (lane == 0) {
        int best = 0; float bv = acc[0] + gb[0];
#pragma unroll
        for (int e = 1; e < NEXP; e++) {
            float v = acc[e] + gb[e];
            if (v > bv) { bv = v; best = e; }
        }
        g_top1[warp] = best;
        g_pos[warp]  = atomicAdd(&g_cnt[best], 1);
    }
}

__global__ void scan_offsets_kernel() {
    int off = 0;
    for (int e = 0; e < NEXP; e++) { g_off[e] = off; off += g_cnt[e]; }
}

__global__ void scatter_kernel() {
    int n = blockIdx.x * blockDim.x + threadIdx.x;
    if (n >= NTOK) return;
    g_perm[g_off[g_top1[n]] + g_pos[n]] = n;
}

// ===================== conversions =====================
__global__ void conv_x_kernel(const float* __restrict__ x) {
    int s = blockIdx.x;
    int tok = g_perm[s];
    int t = threadIdx.x;
    float4 v = reinterpret_cast<const float4*>(x + (size_t)tok * DIM)[t];
    size_t o = (size_t)s * DIM + t * 4;
    reinterpret_cast<__half2*>(g_xa + o)[0] = __half2(__float2half_rn(v.x), __float2half_rn(v.y));
    reinterpret_cast<__half2*>(g_xa + o)[1] = __half2(__float2half_rn(v.z), __float2half_rn(v.w));
}

// weights [e][R][C] fp32 -> transposed [e][C][R] fp16 (K-major for MMA)
template<int R, int C, bool W1>
__global__ void conv_w_kernel(const float* __restrict__ in) {
    __shared__ float tile[32][33];
    int e = blockIdx.z;
    int r0 = blockIdx.y * 32, c0 = blockIdx.x * 32;
    const float* src = in + ((size_t)e * R + r0) * C + c0;
#pragma unroll
    for (int j = threadIdx.y; j < 32; j += 8)
        tile[j][threadIdx.x] = src[(size_t)j * C + threadIdx.x];
    __syncthreads();
    __half* o = (W1 ? g_w1 : g_w2) + ((size_t)e * C + c0) * R + r0;
#pragma unroll
    for (int j = threadIdx.y; j < 32; j += 8)
        o[(size_t)j * R + threadIdx.x] = __float2half_rn(tile[threadIdx.x][j]);
}

// ===================== mma.sync GEMM =====================
// CTA tile 128(M) x 256(N); 8 warps (2M x 4N), warp tile 64x64.
// K chunk = 64 fp16 (128B rows). 4-stage cp.async pipeline (192KB smem).
// Single-pass fp16: C += A*B (fp32 accum).
#define AOFF 0
#define BOFF 16384
#define STAGE 49152
#define NSTAGE 4

template<bool FIRST>
__global__ __launch_bounds__(256, 1)
void moe_gemm(const float* __restrict__ bias,
              const float* __restrict__ x,
              float* __restrict__ out) {
    constexpr int KDIM = FIRST ? DIM : HID;
    constexpr int NDIM = FIRST ? HID : DIM;
    constexpr int NKC  = KDIM / 64;

    const int e  = blockIdx.z;
    const int Me = g_cnt[e];
    const int m0 = blockIdx.y * 128;
    if (m0 >= Me) return;
    const int off = g_off[e];
    const int n0  = blockIdx.x * 256;

    const __half* A = FIRST ? g_xa : g_h;
    const __half* W = (FIRST ? g_w1 : g_w2) + (size_t)e * NDIM * KDIM;

    extern __shared__ char smem[];
    const uint32_t sb = smem_u32(smem);

    const int tid  = threadIdx.x;
    const int lane = tid & 31;
    const int wid  = tid >> 5;
    const int wrow = wid & 1;           // M offset 0/64
    const int wcol = wid >> 1;          // N offset 0/64/128/192

    // ---- async load of one K-chunk into a stage ----
    auto issue_loads = [&](int chunk) {
        const uint32_t base = sb + (chunk % NSTAGE) * STAGE;
        const int k0 = chunk * 64;
        // A: 128 rows x 8 x 16B
#pragma unroll
        for (int w = 0; w < 4; w++) {
            int idx = w * 256 + tid;           // 0..1023
            int row = idx >> 3;                // 0..127
            int c8  = idx & 7;
            uint32_t sw = (uint32_t)(row * 128 + ((c8 * 16) ^ ((row & 7) << 4)));
            cp16(base + AOFF + sw, A + (size_t)(off + m0 + row) * KDIM + k0 + c8 * 8);
        }
        // B: 256 rows x 8 x 16B
#pragma unroll
        for (int w = 0; w < 8; w++) {
            int idx = w * 256 + tid;           // 0..2047
            int row = idx >> 3;                // 0..255
            int c8  = idx & 7;
            uint32_t sw = (uint32_t)(row * 128 + ((c8 * 16) ^ ((row & 7) << 4)));
            cp16(base + BOFF + sw, W + (size_t)(n0 + row) * KDIM + k0 + c8 * 8);
        }
    };

    // ---- per-lane ldmatrix geometry ----
    const int sel = lane >> 3;
    const int l7  = lane & 7;
    const uint32_t lxor = (uint32_t)(l7 << 4);
    uint32_t arow[4], brow[4];
#pragma unroll
    for (int mf = 0; mf < 4; mf++)
        arow[mf] = (uint32_t)((wrow * 64 + mf * 16 + (sel & 1) * 8 + l7) * 128);
#pragma unroll
    for (int nb = 0; nb < 4; nb++)
        brow[nb] = (uint32_t)((wcol * 64 + nb * 16 + (sel >> 1) * 8 + l7) * 128);
    const uint32_t acb = (uint32_t)((sel >> 1) * 16);
    const uint32_t bcb = (uint32_t)((sel & 1) * 16);

    float c[4][8][4];
#pragma unroll
    for (int i = 0; i < 4; i++)
#pragma unroll
        for (int j = 0; j < 8; j++)
#pragma unroll
            for (int r = 0; r < 4; r++) c[i][j][r] = 0.f;

    issue_loads(0); CP_COMMIT();
    issue_loads(1); CP_COMMIT();
    issue_loads(2); CP_COMMIT();

    for (int i = 0; i < NKC; i++) {
        if (i + 3 < NKC) issue_loads(i + 3);
        CP_COMMIT();
        CP_WAIT3();                      // <=3 pending -> chunk i resident
        __syncthreads();

        const uint32_t base = sb + (i % NSTAGE) * STAGE;
#pragma unroll
        for (int kk = 0; kk < 4; kk++) {
            const uint32_t colA = (acb + kk * 32) ^ lxor;
            const uint32_t colB = (bcb + kk * 32) ^ lxor;

            uint32_t Af[4][4], Bf[4][4];
#pragma unroll
            for (int mf = 0; mf < 4; mf++)
                ldsm4(Af[mf][0], Af[mf][1], Af[mf][2], Af[mf][3], base + AOFF + arow[mf] + colA);
#pragma unroll
            for (int nb = 0; nb < 4; nb++)
                ldsm4(Bf[nb][0], Bf[nb][1], Bf[nb][2], Bf[nb][3], base + BOFF + brow[nb] + colB);
#pragma unroll
            for (int mf = 0; mf < 4; mf++)
#pragma unroll
                for (int nb = 0; nb < 4; nb++)
#pragma unroll
                    for (int h = 0; h < 2; h++)
                        mma16816(c[mf][nb*2+h][0], c[mf][nb*2+h][1], c[mf][nb*2+h][2], c[mf][nb*2+h][3],
                                 Af[mf][0], Af[mf][1], Af[mf][2], Af[mf][3],
                                 Bf[nb][2*h], Bf[nb][2*h+1]);
        }
        __syncthreads();
    }

    // ---- epilogue from registers ----
    const int gr = lane >> 2;
    const int gc = (lane & 3) * 2;
    const float* bs = bias + (size_t)e * NDIM;

#pragma unroll
    for (int mf = 0; mf < 4; mf++) {
#pragma unroll
        for (int half = 0; half < 2; half++) {
            const int ml = wrow * 64 + mf * 16 + half * 8 + gr;
            if (m0 + ml >= Me) continue;
            const int slot = off + m0 + ml;
#pragma unroll
            for (int nf = 0; nf < 8; nf++) {
                const int n = n0 + wcol * 64 + nf * 8 + gc;
                const float2 bv = *reinterpret_cast<const float2*>(bs + n);
                float v0 = c[mf][nf][half * 2 + 0] + bv.x;
                float v1 = c[mf][nf][half * 2 + 1] + bv.y;
                if (FIRST) {
                    v0 = fmaxf(v0, 0.f);
                    v1 = fmaxf(v1, 0.f);
                    *reinterpret_cast<__half2*>(g_h + (size_t)slot * HID + n) =
                        __half2(__float2half_rn(v0), __float2half_rn(v1));
                } else {
                    const int tok = g_perm[slot];
                    const float2 xv = *reinterpret_cast<const float2*>(x + (size_t)tok * DIM + n);
                    float2 ov = make_float2(v0 + xv.x, v1 + xv.y);
                    *reinterpret_cast<float2*>(out + (size_t)tok * DIM + n) = ov;
                }
            }
        }
    }
}

// ===================== launch =====================
extern "C" void kernel_launch(void* const* d_in, const int* in_sizes, int n_in,
                              void* d_out, int out_size) {
    const float* x  = (const float*)d_in[0];
    const float* gw = (const float*)d_in[1];
    const float* gb = (const float*)d_in[2];
    const float* w1 = (const float*)d_in[3];
    const float* b1 = (const float*)d_in[4];
    const float* w2 = (const float*)d_in[5];
    const float* b2 = (const float*)d_in[6];
    float* out = (float*)d_out;

    const int SMEM_BYTES = NSTAGE * STAGE;   // 192KB
    cudaFuncSetAttribute(moe_gemm<true>,  cudaFuncAttributeMaxDynamicSharedMemorySize, SMEM_BYTES);
    cudaFuncSetAttribute(moe_gemm<false>, cudaFuncAttributeMaxDynamicSharedMemorySize, SMEM_BYTES);

    zero_counts_kernel<<<1, 32>>>();
    gate_kernel<<<NTOK / 8, 256>>>(x, gw, gb);
    scan_offsets_kernel<<<1, 1>>>();
    scatter_kernel<<<NTOK / 256, 256>>>();

    conv_x_kernel<<<NTOK, 256>>>(x);
    conv_w_kernel<DIM, HID, true ><<<dim3(HID / 32, DIM / 32, NEXP), dim3(32, 8)>>>(w1);
    conv_w_kernel<HID, DIM, false><<<dim3(DIM / 32, HID / 32, NEXP), dim3(32, 8)>>>(w2);

    // GEMM1: [slots x HID], K=DIM
    moe_gemm<true ><<<dim3(HID / 256, NTOK / 128, NEXP), 256, SMEM_BYTES>>>(b1, x, nullptr);
    // GEMM2: [slots x DIM], K=HID
    moe_gemm<false><<<dim3(DIM / 256, NTOK / 128, NEXP), 256, SMEM_BYTES>>>(b2, x, out);
}

// round 7
// speedup vs baseline: 2.4288x; 1.1051x over previous
#include <cuda_runtime.h>
#include <cuda_fp16.h>
#include <cstdint>

#define NTOK 8192
#define DIM  1024
#define NEXP 8
#define HID  4096
#define PADTOK (NTOK + 128)

// ===================== helpers =====================
__device__ __forceinline__ uint32_t smem_u32(const void* p) {
    uint32_t a;
    asm("{ .reg .u64 t; cvta.to.shared.u64 t, %1; cvt.u32.u64 %0, t; }" : "=r"(a) : "l"(p));
    return a;
}
__device__ __forceinline__ void cp16(uint32_t dst, const void* src) {
    asm volatile("cp.async.cg.shared.global [%0], [%1], 16;" :: "r"(dst), "l"(src) : "memory");
}
#define CP_COMMIT() asm volatile("cp.async.commit_group;" ::: "memory")
#define CP_WAIT2()  asm volatile("cp.async.wait_group 2;" ::: "memory")

__device__ __forceinline__ void ldsm4(uint32_t& r0, uint32_t& r1, uint32_t& r2, uint32_t& r3,
                                      uint32_t addr) {
    asm volatile("ldmatrix.sync.aligned.m8n8.x4.shared.b16 {%0,%1,%2,%3}, [%4];"
                 : "=r"(r0), "=r"(r1), "=r"(r2), "=r"(r3) : "r"(addr));
}
__device__ __forceinline__ void mma16816(float& c0, float& c1, float& c2, float& c3,
                                         uint32_t a0, uint32_t a1, uint32_t a2, uint32_t a3,
                                         uint32_t b0, uint32_t b1) {
    asm volatile(
        "mma.sync.aligned.m16n8k16.row.col.f32.f16.f16.f32 "
        "{%0,%1,%2,%3}, {%4,%5,%6,%7}, {%8,%9}, {%0,%1,%2,%3};"
        : "+f"(c0), "+f"(c1), "+f"(c2), "+f"(c3)
        : "r"(a0), "r"(a1), "r"(a2), "r"(a3), "r"(b0), "r"(b1));
}

// ===================== device scratch =====================
__device__ int g_top1[NTOK];
__device__ int g_pos[NTOK];
__device__ int g_cnt[NEXP];
__device__ int g_off[NEXP];
__device__ int g_perm[NTOK];

__device__ __half g_xa[(size_t)PADTOK * DIM];       // permuted x, fp16
__device__ __half g_h[(size_t)PADTOK * HID];        // hidden, fp16
__device__ __half g_w1[(size_t)NEXP * HID * DIM];   // [e][n(HID)][k(DIM)]
__device__ __half g_w2[(size_t)NEXP * DIM * HID];   // [e][n(DIM)][k(HID)]

// ===================== gating =====================
__global__ void zero_counts_kernel() {
    if (threadIdx.x < NEXP) g_cnt[threadIdx.x] = 0;
}

__global__ void gate_kernel(const float* __restrict__ x,
                            const float* __restrict__ gw,
                            const float* __restrict__ gb) {
    int warp = blockIdx.x * (blockDim.x / 32) + (threadIdx.x >> 5);
    int lane = threadIdx.x & 31;
    if (warp >= NTOK) return;
    const float* xr = x + (size_t)warp * DIM;
    float acc[NEXP];
#pragma unroll
    for (int e = 0; e < NEXP; e++) acc[e] = 0.f;
    for (int d = lane; d < DIM; d += 32) {
        float xv = xr[d];
        const float4* g4 = reinterpret_cast<const float4*>(gw + (size_t)d * NEXP);
        float4 g0 = g4[0], g1 = g4[1];
        acc[0] += xv * g0.x; acc[1] += xv * g0.y; acc[2] += xv * g0.z; acc[3] += xv * g0.w;
        acc[4] += xv * g1.x; acc[5] += xv * g1.y; acc[6] += xv * g1.z; acc[7] += xv * g1.w;
    }
#pragma unroll
    for (int e = 0; e < NEXP; e++) {
#pragma unroll
        for (int o = 16; o > 0; o >>= 1) acc[e] += __shfl_xor_sync(0xffffffffu, acc[e], o);
    }
    if (lane == 0) {
        int best = 0; float bv = acc[0] + gb[0];
#pragma unroll
        for (int e = 1; e < NEXP; e++) {
            float v = acc[e] + gb[e];
            if (v > bv) { bv = v; best = e; }
        }
        g_top1[warp] = best;
        g_pos[warp]  = atomicAdd(&g_cnt[best], 1);
    }
}

__global__ void scan_offsets_kernel() {
    int off = 0;
    for (int e = 0; e < NEXP; e++) { g_off[e] = off; off += g_cnt[e]; }
}

__global__ void scatter_kernel() {
    int n = blockIdx.x * blockDim.x + threadIdx.x;
    if (n >= NTOK) return;
    g_perm[g_off[g_top1[n]] + g_pos[n]] = n;
}

// ===================== conversions =====================
__global__ void conv_x_kernel(const float* __restrict__ x) {
    int s = blockIdx.x;
    int tok = g_perm[s];
    int t = threadIdx.x;
    float4 v = reinterpret_cast<const float4*>(x + (size_t)tok * DIM)[t];
    size_t o = (size_t)s * DIM + t * 4;
    reinterpret_cast<__half2*>(g_xa + o)[0] = __half2(__float2half_rn(v.x), __float2half_rn(v.y));
    reinterpret_cast<__half2*>(g_xa + o)[1] = __half2(__float2half_rn(v.z), __float2half_rn(v.w));
}

// weights [e][R][C] fp32 -> transposed [e][C][R] fp16 (K-major for MMA)
template<int R, int C, bool W1>
__global__ void conv_w_kernel(const float* __restrict__ in) {
    __shared__ float tile[32][33];
    int e = blockIdx.z;
    int r0 = blockIdx.y * 32, c0 = blockIdx.x * 32;
    const float* src = in + ((size_t)e * R + r0) * C + c0;
#pragma unroll
    for (int j = threadIdx.y; j < 32; j += 8)
        tile[j][threadIdx.x] = src[(size_t)j * C + threadIdx.x];
    __syncthreads();
    __half* o = (W1 ? g_w1 : g_w2) + ((size_t)e * C + c0) * R + r0;
#pragma unroll
    for (int j = threadIdx.y; j < 32; j += 8)
        o[(size_t)j * R + threadIdx.x] = __float2half_rn(tile[threadIdx.x][j]);
}

// ===================== mma.sync GEMM =====================
// CTA tile 128(M) x 128(N); 4 warps (2M x 2N), warp tile 64x64.
// K chunk = 64 fp16 (128B rows). 3-stage cp.async pipeline, 32KB stages
// (96KB smem) -> 2 CTAs/SM for cross-CTA bubble filling.
// Single-pass fp16: C += A*B (fp32 accum). Zero LDSM redundancy.
#define AOFF 0
#define BOFF 16384
#define STAGE 32768
#define NSTAGE 3

template<bool FIRST>
__global__ __launch_bounds__(128, 2)
void moe_gemm(const float* __restrict__ bias,
              const float* __restrict__ x,
              float* __restrict__ out) {
    constexpr int KDIM = FIRST ? DIM : HID;
    constexpr int NDIM = FIRST ? HID : DIM;
    constexpr int NKC  = KDIM / 64;

    const int e  = blockIdx.z;
    const int Me = g_cnt[e];
    const int m0 = blockIdx.y * 128;
    if (m0 >= Me) return;
    const int off = g_off[e];
    const int n0  = blockIdx.x * 128;

    const __half* A = FIRST ? g_xa : g_h;
    const __half* W = (FIRST ? g_w1 : g_w2) + (size_t)e * NDIM * KDIM;

    extern __shared__ char smem[];
    const uint32_t sb = smem_u32(smem);

    const int tid  = threadIdx.x;
    const int lane = tid & 31;
    const int wid  = tid >> 5;
    const int wrow = wid & 1;           // M offset 0/64
    const int wcol = wid >> 1;          // N offset 0/64

    // ---- async load of one K-chunk into a stage (A 16KB + B 16KB) ----
    auto issue_loads = [&](int chunk) {
        const uint32_t base = sb + (chunk % NSTAGE) * STAGE;
        const int k0 = chunk * 64;
#pragma unroll
        for (int w = 0; w < 8; w++) {
            int idx = w * 128 + tid;           // 0..1023
            int row = idx >> 3;                // 0..127
            int c8  = idx & 7;
            uint32_t sw = (uint32_t)(row * 128 + ((c8 * 16) ^ ((row & 7) << 4)));
            cp16(base + AOFF + sw, A + (size_t)(off + m0 + row) * KDIM + k0 + c8 * 8);
            cp16(base + BOFF + sw, W + (size_t)(n0 + row) * KDIM + k0 + c8 * 8);
        }
    };

    // ---- per-lane ldmatrix geometry ----
    const int sel = lane >> 3;
    const int l7  = lane & 7;
    const uint32_t lxor = (uint32_t)(l7 << 4);
    uint32_t arow[4], brow[4];
#pragma unroll
    for (int mf = 0; mf < 4; mf++)
        arow[mf] = (uint32_t)((wrow * 64 + mf * 16 + (sel & 1) * 8 + l7) * 128);
#pragma unroll
    for (int nb = 0; nb < 4; nb++)
        brow[nb] = (uint32_t)((wcol * 64 + nb * 16 + (sel >> 1) * 8 + l7) * 128);
    const uint32_t acb = (uint32_t)((sel >> 1) * 16);
    const uint32_t bcb = (uint32_t)((sel & 1) * 16);

    float c[4][8][4];
#pragma unroll
    for (int i = 0; i < 4; i++)
#pragma unroll
        for (int j = 0; j < 8; j++)
#pragma unroll
            for (int r = 0; r < 4; r++) c[i][j][r] = 0.f;

    issue_loads(0); CP_COMMIT();
    issue_loads(1); CP_COMMIT();

    for (int i = 0; i < NKC; i++) {
        if (i + 2 < NKC) issue_loads(i + 2);
        CP_COMMIT();
        CP_WAIT2();                      // <=2 pending -> chunk i resident
        __syncthreads();

        const uint32_t base = sb + (i % NSTAGE) * STAGE;
#pragma unroll
        for (int kk = 0; kk < 4; kk++) {
            const uint32_t colA = (acb + kk * 32) ^ lxor;
            const uint32_t colB = (bcb + kk * 32) ^ lxor;

            uint32_t Af[4][4], Bf[4][4];
#pragma unroll
            for (int mf = 0; mf < 4; mf++)
                ldsm4(Af[mf][0], Af[mf][1], Af[mf][2], Af[mf][3], base + AOFF + arow[mf] + colA);
#pragma unroll
            for (int nb = 0; nb < 4; nb++)
                ldsm4(Bf[nb][0], Bf[nb][1], Bf[nb][2], Bf[nb][3], base + BOFF + brow[nb] + colB);
#pragma unroll
            for (int mf = 0; mf < 4; mf++)
#pragma unroll
                for (int nb = 0; nb < 4; nb++)
#pragma unroll
                    for (int h = 0; h < 2; h++)
                        mma16816(c[mf][nb*2+h][0], c[mf][nb*2+h][1], c[mf][nb*2+h][2], c[mf][nb*2+h][3],
                                 Af[mf][0], Af[mf][1], Af[mf][2], Af[mf][3],
                                 Bf[nb][2*h], Bf[nb][2*h+1]);
        }
        __syncthreads();
    }

    // ---- epilogue from registers ----
    const int gr = lane >> 2;
    const int gc = (lane & 3) * 2;
    const float* bs = bias + (size_t)e * NDIM;

#pragma unroll
    for (int mf = 0; mf < 4; mf++) {
#pragma unroll
        for (int half = 0; half < 2; half++) {
            const int ml = wrow * 64 + mf * 16 + half * 8 + gr;
            if (m0 + ml >= Me) continue;
            const int slot = off + m0 + ml;
#pragma unroll
            for (int nf = 0; nf < 8; nf++) {
                const int n = n0 + wcol * 64 + nf * 8 + gc;
                const float2 bv = *reinterpret_cast<const float2*>(bs + n);
                float v0 = c[mf][nf][half * 2 + 0] + bv.x;
                float v1 = c[mf][nf][half * 2 + 1] + bv.y;
                if (FIRST) {
                    v0 = fmaxf(v0, 0.f);
                    v1 = fmaxf(v1, 0.f);
                    *reinterpret_cast<__half2*>(g_h + (size_t)slot * HID + n) =
                        __half2(__float2half_rn(v0), __float2half_rn(v1));
                } else {
                    const int tok = g_perm[slot];
                    const float2 xv = *reinterpret_cast<const float2*>(x + (size_t)tok * DIM + n);
                    float2 ov = make_float2(v0 + xv.x, v1 + xv.y);
                    *reinterpret_cast<float2*>(out + (size_t)tok * DIM + n) = ov;
                }
            }
        }
    }
}

// ===================== launch =====================
extern "C" void kernel_launch(void* const* d_in, const int* in_sizes, int n_in,
                              void* d_out, int out_size) {
    const float* x  = (const float*)d_in[0];
    const float* gw = (const float*)d_in[1];
    const float* gb = (const float*)d_in[2];
    const float* w1 = (const float*)d_in[3];
    const float* b1 = (const float*)d_in[4];
    const float* w2 = (const float*)d_in[5];
    const float* b2 = (const float*)d_in[6];
    float* out = (float*)d_out;

    const int SMEM_BYTES = NSTAGE * STAGE;   // 96KB -> 2 CTAs/SM
    cudaFuncSetAttribute(moe_gemm<true>,  cudaFuncAttributeMaxDynamicSharedMemorySize, SMEM_BYTES);
    cudaFuncSetAttribute(moe_gemm<false>, cudaFuncAttributeMaxDynamicSharedMemorySize, SMEM_BYTES);

    zero_counts_kernel<<<1, 32>>>();
    gate_kernel<<<NTOK / 8, 256>>>(x, gw, gb);
    scan_offsets_kernel<<<1, 1>>>();
    scatter_kernel<<<NTOK / 256, 256>>>();

    conv_x_kernel<<<NTOK, 256>>>(x);
    conv_w_kernel<DIM, HID, true ><<<dim3(HID / 32, DIM / 32, NEXP), dim3(32, 8)>>>(w1);
    conv_w_kernel<HID, DIM, false><<<dim3(DIM / 32, HID / 32, NEXP), dim3(32, 8)>>>(w2);

    // GEMM1: [slots x HID], K=DIM
    moe_gemm<true ><<<dim3(HID / 128, NTOK / 128, NEXP), 128, SMEM_BYTES>>>(b1, x, nullptr);
    // GEMM2: [slots x DIM], K=HID
    moe_gemm<false><<<dim3(DIM / 128, NTOK / 128, NEXP), 128, SMEM_BYTES>>>(b2, x, out);
}